// round 4
// baseline (speedup 1.0000x reference)
#include <cuda_runtime.h>
#include <cstdint>

#define BSZ   2
#define DM    1536
#define LSEQ  2048
#define NST   16
#define CHUNK 64
#define KCH   (LSEQ/CHUNK)   /* 32 */
#define DBLK  128
#define NDBLK (DM/DBLK)      /* 12 */

// Scratch: per-chunk decay products, local final states, corrected initial states.
// Layout [b, k, d, n] for coalesced fixup access.
__device__ float g_P [BSZ*KCH*DM*NST];
__device__ float g_hl[BSZ*KCH*DM*NST];
__device__ float g_hi[BSZ*KCH*DM*NST];

__device__ __forceinline__ float ex2f(float v){
    float r; asm("ex2.approx.ftz.f32 %0, %1;" : "=f"(r) : "f"(v)); return r;
}

// ---------------------------------------------------------------------------
// Pass 1: per (b, chunk, d) compute P_n = prod a_t and h_local_n (scan from 0).
// ---------------------------------------------------------------------------
__global__ __launch_bounds__(DBLK) void ssm_pass1(
    const float* __restrict__ x, const float* __restrict__ delta,
    const float* __restrict__ A, const float* __restrict__ Bmat)
{
    __shared__ float Bs[CHUNK*NST];
    const int tid = threadIdx.x;
    const int d   = blockIdx.x * DBLK + tid;
    const int k   = blockIdx.y;
    const int b   = blockIdx.z;
    const int l0  = k * CHUNK;

    // Stage B[b, 0..15, l0..l0+63] -> Bs[j][n]  (coalesced gmem reads)
    const float* Bg = Bmat + ((size_t)b*NST)*LSEQ + l0;
    #pragma unroll
    for (int i = 0; i < (CHUNK*NST)/DBLK; ++i){
        int e = tid + i*DBLK;
        int n = e >> 6, j = e & (CHUNK-1);
        Bs[j*NST + n] = Bg[(size_t)n*LSEQ + j];
    }
    __syncthreads();

    float Alc[NST];
    {
        const float4* Ar = reinterpret_cast<const float4*>(A + (size_t)d*NST);
        const float L2E = 1.4426950408889634f;
        #pragma unroll
        for (int i=0;i<4;i++){
            float4 v = Ar[i];
            Alc[4*i+0]=v.x*L2E; Alc[4*i+1]=v.y*L2E;
            Alc[4*i+2]=v.z*L2E; Alc[4*i+3]=v.w*L2E;
        }
    }

    float h[NST], P[NST];
    #pragma unroll
    for (int n=0;n<NST;n++){ h[n]=0.f; P[n]=1.f; }

    const size_t rowoff = ((size_t)b*DM + d)*LSEQ + l0;
    const float4* xp = reinterpret_cast<const float4*>(x + rowoff);
    const float4* dp = reinterpret_cast<const float4*>(delta + rowoff);

    #pragma unroll 4
    for (int j4 = 0; j4 < CHUNK/4; ++j4){
        float4 dv = dp[j4];
        float4 xv = xp[j4];
        float dls[4] = {dv.x, dv.y, dv.z, dv.w};
        float xls[4] = {xv.x, xv.y, xv.z, xv.w};
        #pragma unroll
        for (int q=0;q<4;q++){
            float dl = dls[q];
            float dx = dl * xls[q];
            const float4* Br = reinterpret_cast<const float4*>(Bs + (j4*4+q)*NST);
            #pragma unroll
            for (int i=0;i<4;i++){
                float4 bv = Br[i];
                float a0 = ex2f(dl*Alc[4*i+0]);
                float a1 = ex2f(dl*Alc[4*i+1]);
                float a2 = ex2f(dl*Alc[4*i+2]);
                float a3 = ex2f(dl*Alc[4*i+3]);
                h[4*i+0] = fmaf(a0, h[4*i+0], dx*bv.x);
                h[4*i+1] = fmaf(a1, h[4*i+1], dx*bv.y);
                h[4*i+2] = fmaf(a2, h[4*i+2], dx*bv.z);
                h[4*i+3] = fmaf(a3, h[4*i+3], dx*bv.w);
                P[4*i+0]*=a0; P[4*i+1]*=a1; P[4*i+2]*=a2; P[4*i+3]*=a3;
            }
        }
    }

    size_t base = (((size_t)b*KCH + k)*DM + d)*NST;
    float4* Pp = reinterpret_cast<float4*>(g_P  + base);
    float4* Hp = reinterpret_cast<float4*>(g_hl + base);
    #pragma unroll
    for (int i=0;i<4;i++){
        Pp[i] = make_float4(P[4*i],P[4*i+1],P[4*i+2],P[4*i+3]);
        Hp[i] = make_float4(h[4*i],h[4*i+1],h[4*i+2],h[4*i+3]);
    }
}

// ---------------------------------------------------------------------------
// Fixup: one thread per (b,d,n), serially chain the 32 chunks.
// h_init(k) = state before chunk k.  Coalesced: consecutive threads = (d,n).
// ---------------------------------------------------------------------------
__global__ void ssm_fixup()
{
    int gid = blockIdx.x * blockDim.x + threadIdx.x;  // < BSZ*DM*NST
    int n = gid % NST;
    int d = (gid / NST) % DM;
    int b = gid / (NST * DM);
    float h = 0.f;
    const size_t stride = (size_t)DM * NST;
    size_t idx = ((size_t)b*KCH*DM + d)*NST + n;
    #pragma unroll 4
    for (int k = 0; k < KCH; ++k){
        g_hi[idx] = h;
        h = fmaf(g_P[idx], h, g_hl[idx]);
        idx += stride;
    }
}

// ---------------------------------------------------------------------------
// Pass 2: rescan each chunk from corrected h_init; emit full output.
// ---------------------------------------------------------------------------
__global__ __launch_bounds__(DBLK) void ssm_pass2(
    const float* __restrict__ x, const float* __restrict__ delta,
    const float* __restrict__ A, const float* __restrict__ Bmat,
    const float* __restrict__ Cmat, const float* __restrict__ Dvec,
    const float* __restrict__ z, float* __restrict__ out)
{
    __shared__ float Bs[CHUNK*NST];
    __shared__ float Cs[CHUNK*NST];
    const int tid = threadIdx.x;
    const int d   = blockIdx.x * DBLK + tid;
    const int k   = blockIdx.y;
    const int b   = blockIdx.z;
    const int l0  = k * CHUNK;

    const float* Bg = Bmat + ((size_t)b*NST)*LSEQ + l0;
    const float* Cg = Cmat + ((size_t)b*NST)*LSEQ + l0;
    #pragma unroll
    for (int i = 0; i < (CHUNK*NST)/DBLK; ++i){
        int e = tid + i*DBLK;
        int n = e >> 6, j = e & (CHUNK-1);
        Bs[j*NST + n] = Bg[(size_t)n*LSEQ + j];
        Cs[j*NST + n] = Cg[(size_t)n*LSEQ + j];
    }
    __syncthreads();

    float Alc[NST];
    {
        const float4* Ar = reinterpret_cast<const float4*>(A + (size_t)d*NST);
        const float L2E = 1.4426950408889634f;
        #pragma unroll
        for (int i=0;i<4;i++){
            float4 v = Ar[i];
            Alc[4*i+0]=v.x*L2E; Alc[4*i+1]=v.y*L2E;
            Alc[4*i+2]=v.z*L2E; Alc[4*i+3]=v.w*L2E;
        }
    }

    float h[NST];
    {
        size_t base = (((size_t)b*KCH + k)*DM + d)*NST;
        const float4* Hp = reinterpret_cast<const float4*>(g_hi + base);
        #pragma unroll
        for (int i=0;i<4;i++){
            float4 v = Hp[i];
            h[4*i+0]=v.x; h[4*i+1]=v.y; h[4*i+2]=v.z; h[4*i+3]=v.w;
        }
    }
    const float Dd = Dvec[d];

    const size_t rowoff = ((size_t)b*DM + d)*LSEQ + l0;
    const float4* xp = reinterpret_cast<const float4*>(x + rowoff);
    const float4* dp = reinterpret_cast<const float4*>(delta + rowoff);
    const float4* zp = reinterpret_cast<const float4*>(z + rowoff);
    float4* op = reinterpret_cast<float4*>(out + rowoff);

    #pragma unroll 2
    for (int j4 = 0; j4 < CHUNK/4; ++j4){
        float4 dv = dp[j4];
        float4 xv = xp[j4];
        float4 zv = zp[j4];
        float dls[4] = {dv.x, dv.y, dv.z, dv.w};
        float xls[4] = {xv.x, xv.y, xv.z, xv.w};
        float zls[4] = {zv.x, zv.y, zv.z, zv.w};
        float ovv[4];
        #pragma unroll
        for (int q=0;q<4;q++){
            float dl = dls[q];
            float dx = dl * xls[q];
            const float4* Br = reinterpret_cast<const float4*>(Bs + (j4*4+q)*NST);
            const float4* Cr = reinterpret_cast<const float4*>(Cs + (j4*4+q)*NST);
            float y = 0.f;
            #pragma unroll
            for (int i=0;i<4;i++){
                float4 bv = Br[i];
                float4 cv = Cr[i];
                float a0 = ex2f(dl*Alc[4*i+0]);
                float a1 = ex2f(dl*Alc[4*i+1]);
                float a2 = ex2f(dl*Alc[4*i+2]);
                float a3 = ex2f(dl*Alc[4*i+3]);
                h[4*i+0] = fmaf(a0, h[4*i+0], dx*bv.x);
                h[4*i+1] = fmaf(a1, h[4*i+1], dx*bv.y);
                h[4*i+2] = fmaf(a2, h[4*i+2], dx*bv.z);
                h[4*i+3] = fmaf(a3, h[4*i+3], dx*bv.w);
                y = fmaf(h[4*i+0], cv.x, y);
                y = fmaf(h[4*i+1], cv.y, y);
                y = fmaf(h[4*i+2], cv.z, y);
                y = fmaf(h[4*i+3], cv.w, y);
            }
            float pre = fmaf(xls[q], Dd, y);            // y + x*D
            float zz  = zls[q];
            float e   = ex2f(-1.4426950408889634f * zz); // exp(-z)
            float sg  = __fdividef(1.f, 1.f + e);        // sigmoid(z)
            ovv[q] = pre * zz * sg;                      // * silu(z)
        }
        op[j4] = make_float4(ovv[0], ovv[1], ovv[2], ovv[3]);
    }
}

extern "C" void kernel_launch(void* const* d_in, const int* in_sizes, int n_in,
                              void* d_out, int out_size)
{
    const float* x     = (const float*)d_in[0];
    const float* delta = (const float*)d_in[1];
    const float* A     = (const float*)d_in[2];
    const float* Bm    = (const float*)d_in[3];
    const float* Cm    = (const float*)d_in[4];
    const float* Dv    = (const float*)d_in[5];
    const float* z     = (const float*)d_in[6];
    float* out = (float*)d_out;

    dim3 grid(NDBLK, KCH, BSZ);   // 12 x 32 x 2 = 768 blocks
    ssm_pass1<<<grid, DBLK>>>(x, delta, A, Bm);
    ssm_fixup<<<(BSZ*DM*NST)/256, 256>>>();
    ssm_pass2<<<grid, DBLK>>>(x, delta, A, Bm, Cm, Dv, z, out);
}